// round 15
// baseline (speedup 1.0000x reference)
#include <cuda_runtime.h>
#include <cstdint>

#define NN   4
#define C    256
#define H    64
#define W    64
#define P    (H*W)
#define CCH  64
#define K2   25
#define HO   128
#define WO   128
#define ENC  100

typedef unsigned long long u64;
typedef unsigned int u32;

__device__ __forceinline__ u64 pack2(float lo, float hi) {
    u64 r; asm("mov.b64 %0, {%1,%2};" : "=l"(r) : "f"(lo), "f"(hi)); return r;
}
__device__ __forceinline__ u64 dup2(float v) {
    u64 r; asm("mov.b64 %0, {%1,%1};" : "=l"(r) : "f"(v)); return r;
}
__device__ __forceinline__ void unpack2(u64 v, float& lo, float& hi) {
    asm("mov.b64 {%0,%1}, %2;" : "=f"(lo), "=f"(hi) : "l"(v));
}
__device__ __forceinline__ u64 fma2(u64 a, u64 b, u64 c) {
    u64 d; asm("fma.rn.f32x2 %0, %1, %2, %3;" : "=l"(d) : "l"(a), "l"(b), "l"(c)); return d;
}
__device__ __forceinline__ u64 add2(u64 a, u64 b) {
    u64 d; asm("add.rn.f32x2 %0, %1, %2;" : "=l"(d) : "l"(a), "l"(b)); return d;
}
__device__ __forceinline__ void cp4(u32 dst, const float* src) {
    asm volatile("cp.async.ca.shared.global [%0], [%1], 4;" :: "r"(dst), "l"(src));
}
__device__ __forceinline__ void cp16(u32 dst, const float* src) {
    asm volatile("cp.async.cg.shared.global [%0], [%1], 16;" :: "r"(dst), "l"(src));
}

// scratch (device globals; no allocations allowed)
__device__ float g_comp[NN*CCH*P];           // 4 MB
__device__ float g_m[NN*ENC*P];              // encoder logits, K-half 0
__device__ float g_m2[NN*ENC*P];             // encoder logits, K-half 1
__device__ float g_wt[C*CCH];                // transposed compressor weights
__device__ float2 g_wp[4*8*1152];            // packed encoder weights

// ---------------------------------------------------------------------------
// Kernel T: transpose Wc (64,256) -> g_wt (256,64)
// ---------------------------------------------------------------------------
__global__ void k_transpose(const float* __restrict__ Wc) {
    int idx = blockIdx.x * 256 + threadIdx.x;
    int oc = idx & 63, c = idx >> 6;
    g_wt[c*CCH + oc] = Wc[oc*C + c];
}

// ---------------------------------------------------------------------------
// Kernel P: pack encoder weights: We[100][64][9] ->
// g_wp[ocg 4][round 8][c 8][tap 9][slot 16] float2.
// slot = og*8 + j (j 0..6 used): oc pair index qq = og*7 + j.
// ---------------------------------------------------------------------------
__global__ void k_wpack(const float* __restrict__ We) {
    int idx = blockIdx.x * 256 + threadIdx.x;    // 36864 entries
    if (idx >= 4*8*1152) return;
    int slot = idx % 16;
    int tap  = (idx / 16) % 9;
    int c    = (idx / 144) % 8;
    int r    = (idx / 1152) % 8;
    int ocg  = idx / 9216;
    int og = slot >> 3, j = slot & 7;
    int qq = og*7 + j;
    int cs = r*8 + c;
    int oc = ocg*25 + 2*qq;
    float wa = 0.f, wb = 0.f;
    if (j < 7) {
        if (2*qq     < 25) wa = We[(oc*CCH + cs)*9 + tap];
        if (2*qq + 1 < 25) wb = We[((oc + 1)*CCH + cs)*9 + tap];
    }
    g_wp[idx] = make_float2(wa, wb);
}

// ---------------------------------------------------------------------------
// Kernel A: 1x1 conv compressor, 64oc x 32px tiles, packed f32x2 over px.
// ---------------------------------------------------------------------------
__global__ __launch_bounds__(128)
void k_compress(const float* __restrict__ x, const float* __restrict__ bc) {
    __shared__ __align__(16) float Ws[16][64];
    __shared__ __align__(16) float Xs[16][32];
    const int n  = blockIdx.y;
    const int p0 = blockIdx.x * 32;
    const int tx = threadIdx.x & 7;
    const int ty = threadIdx.x >> 3;

    u64 acc[4][2];
#pragma unroll
    for (int i = 0; i < 4; i++) { acc[i][0] = 0ull; acc[i][1] = 0ull; }

    for (int c0 = 0; c0 < C; c0 += 16) {
        __syncthreads();
        for (int i = threadIdx.x; i < 1024; i += 128) {
            int k = i >> 6, oc = i & 63;
            Ws[k][oc] = g_wt[(c0 + k)*CCH + oc];
        }
        for (int i = threadIdx.x; i < 512; i += 128) {
            int k = i >> 5, px = i & 31;
            Xs[k][px] = x[(n*C + c0 + k)*P + p0 + px];
        }
        __syncthreads();
#pragma unroll
        for (int k = 0; k < 16; k++) {
            float4 a = *(const float4*)&Ws[k][ty*4];
            u64 b01 = *(const u64*)&Xs[k][tx*4];
            u64 b23 = *(const u64*)&Xs[k][tx*4 + 2];
            float av[4] = {a.x, a.y, a.z, a.w};
#pragma unroll
            for (int i = 0; i < 4; i++) {
                u64 d = dup2(av[i]);
                acc[i][0] = fma2(d, b01, acc[i][0]);
                acc[i][1] = fma2(d, b23, acc[i][1]);
            }
        }
    }
#pragma unroll
    for (int i = 0; i < 4; i++) {
        int oc = ty*4 + i;
        u64 bd = dup2(bc[oc]);
        float* p = &g_comp[(n*CCH + oc)*P + p0 + tx*4];
        *(u64*)p       = add2(acc[i][0], bd);
        *(u64*)(p + 2) = add2(acc[i][1], bd);
    }
}

// ---------------------------------------------------------------------------
// Kernel B: 3x3 conv encoder. 256 threads = 2 oc-groups x (2px x 8x16 tile).
// og=0 -> oc pairs 0..6, og=1 -> pairs 7..13 (guarded). K-split (kh) 32 ch.
// cp.async double-buffered tile+weights. 7 packed accs x 2px per thread.
// grid (16 tiles, 4 n, 4 ocg x 2 kh) = 512 blocks x 256 thr = 27.7 warps/SM.
// ---------------------------------------------------------------------------
__global__ __launch_bounds__(256)
void k_encode(const float* __restrict__ be) {
    __shared__ __align__(16) float tile[2][8*324];    // [c][18][18]
    __shared__ __align__(16) float2 wgt2[2][1152];    // [c][tap][16 slots]
    const int bx = blockIdx.x;
    const int h0 = (bx >> 2) * 16;
    const int w0 = (bx & 3) * 16;
    const int n  = blockIdx.y;
    const int ocg = blockIdx.z & 3;
    const int kh  = blockIdx.z >> 2;
    const int oc0 = ocg * 25;
    const int og  = threadIdx.x >> 7;      // 0/1 oc half
    const int t128 = threadIdx.x & 127;
    const int xg = t128 & 7;
    const int ty = t128 >> 3;              // 0..15

    // staging geometry (2 slots per thread, round-invariant)
    int sps[2]; bool oks[2];
#pragma unroll
    for (int j = 0; j < 2; j++) {
        int q = threadIdx.x + j*256;
        oks[j] = false; sps[j] = 0;
        if (q < 324) {
            int yy = q / 18, xw = q % 18;
            int gy = h0 + yy - 1, gx = w0 + xw - 1;
            if (gy >= 0 && gy < H && gx >= 0 && gx < W) {
                oks[j] = true; sps[j] = gy*W + gx;
            } else {
#pragma unroll
                for (int c = 0; c < 8; c++) {
                    tile[0][c*324 + q] = 0.f;
                    tile[1][c*324 + q] = 0.f;
                }
            }
        }
    }
    const float* cb = g_comp + n*CCH*P + kh*32*P;
    const float* wb = (const float*)(g_wp + ocg*9216 + kh*4608);

    u32 ta[2], wa[2];
    ta[0] = (u32)__cvta_generic_to_shared(&tile[0][0]);
    ta[1] = (u32)__cvta_generic_to_shared(&tile[1][0]);
    wa[0] = (u32)__cvta_generic_to_shared(&wgt2[0][0]);
    wa[1] = (u32)__cvta_generic_to_shared(&wgt2[1][0]);

    // stage round 0
#pragma unroll
    for (int j = 0; j < 2; j++) if (oks[j]) {
        int q = threadIdx.x + j*256;
#pragma unroll
        for (int c = 0; c < 8; c++)
            cp4(ta[0] + (c*324 + q)*4, cb + c*P + sps[j]);
    }
    for (int i = threadIdx.x; i < 576; i += 256)
        cp16(wa[0] + i*16, wb + i*4);
    asm volatile("cp.async.commit_group;");

    u64 accA[7], accB[7];
#pragma unroll
    for (int q = 0; q < 7; q++) { accA[q] = 0ull; accB[q] = 0ull; }

    for (int r = 0; r < 4; r++) {
        asm volatile("cp.async.wait_group 0;");
        __syncthreads();
        if (r < 3) {
            int nb = (r + 1) & 1;
            const float* cbn = cb + (r + 1)*8*P;
#pragma unroll
            for (int j = 0; j < 2; j++) if (oks[j]) {
                int q = threadIdx.x + j*256;
#pragma unroll
                for (int c = 0; c < 8; c++)
                    cp4(ta[nb] + (c*324 + q)*4, cbn + c*P + sps[j]);
            }
            const float* wbn = wb + (r + 1)*2304;   // 1152 float2 per round
            for (int i = threadIdx.x; i < 576; i += 256)
                cp16(wa[nb] + i*16, wbn + i*4);
            asm volatile("cp.async.commit_group;");
        }
        const float* tb = tile[r & 1];
        const float2* wg = wgt2[r & 1];
#pragma unroll 1
        for (int c = 0; c < 8; c++) {
            const int base = c*324 + ty*18 + xg*2;
#pragma unroll
            for (int ky = 0; ky < 3; ky++) {
                float2 fa = *(const float2*)&tb[base + ky*18];
                float2 fb = *(const float2*)&tb[base + ky*18 + 2];
                u64 dv[4];
                dv[0] = dup2(fa.x); dv[1] = dup2(fa.y);
                dv[2] = dup2(fb.x); dv[3] = dup2(fb.y);
#pragma unroll
                for (int kx = 0; kx < 3; kx++) {
                    u64 v0 = dv[kx];
                    u64 v1 = dv[kx + 1];
                    const float2* wp = &wg[(c*9 + ky*3 + kx)*16 + og*8];
                    ulonglong2 w01 = *(const ulonglong2*)(wp);
                    ulonglong2 w23 = *(const ulonglong2*)(wp + 2);
                    ulonglong2 w45 = *(const ulonglong2*)(wp + 4);
                    u64 w6 = *(const u64*)(wp + 6);
                    accA[0] = fma2(v0, w01.x, accA[0]); accB[0] = fma2(v1, w01.x, accB[0]);
                    accA[1] = fma2(v0, w01.y, accA[1]); accB[1] = fma2(v1, w01.y, accB[1]);
                    accA[2] = fma2(v0, w23.x, accA[2]); accB[2] = fma2(v1, w23.x, accB[2]);
                    accA[3] = fma2(v0, w23.y, accA[3]); accB[3] = fma2(v1, w23.y, accB[3]);
                    accA[4] = fma2(v0, w45.x, accA[4]); accB[4] = fma2(v1, w45.x, accB[4]);
                    accA[5] = fma2(v0, w45.y, accA[5]); accB[5] = fma2(v1, w45.y, accB[5]);
                    accA[6] = fma2(v0, w6,    accA[6]); accB[6] = fma2(v1, w6,    accB[6]);
                }
            }
        }
        __syncthreads();
    }

    float* __restrict__ gout = kh ? g_m2 : g_m;
    const int y = h0 + ty, xpx = w0 + xg*2;
#pragma unroll
    for (int q = 0; q < 7; q++) {
        int qq = og*7 + q;
        int ocl = 2*qq;
        if (ocl >= 25) break;
        int oc = oc0 + ocl;
        float a0, a1, b0, b1;
        unpack2(accA[q], a0, a1);
        unpack2(accB[q], b0, b1);
        float bias0 = kh ? 0.f : be[oc];
        *(float2*)&gout[(n*ENC + oc)*P + y*W + xpx] = make_float2(a0 + bias0, b0 + bias0);
        if (ocl + 1 < 25) {
            float bias1 = kh ? 0.f : be[oc + 1];
            *(float2*)&gout[(n*ENC + oc + 1)*P + y*W + xpx] = make_float2(a1 + bias1, b1 + bias1);
        }
    }
}

// ---------------------------------------------------------------------------
// Kernel D: fused softmax + reassembly (scheme W, g_m + g_m2 sum).
// ---------------------------------------------------------------------------
__global__ __launch_bounds__(256)
void k_reassemble(const float* __restrict__ x, float* __restrict__ out) {
    __shared__ float ms[ENC*65];
    __shared__ __align__(16) float xs[2][144*18];   // [spatial][ch pad 18]
    const int t   = blockIdx.x;
    const int n   = blockIdx.y;
    const int c00 = blockIdx.z * 64;
    const int h0 = (t >> 3) * 8, w0 = (t & 7) * 8;
    const int s  = threadIdx.x & 3;
    const int p  = threadIdx.x >> 2;
    const int h  = p >> 3, w = p & 7;
    const int gh = h0 + h, gw = w0 + w;
    const int si = s >> 1, sj = s & 1;

    int sp = -1;
    if (threadIdx.x < 144) {
        int yy = threadIdx.x / 12, xw = threadIdx.x % 12;
        int gy = h0 + yy - 2, gx = w0 + xw - 2;
        if (gy >= 0 && gy < H && gx >= 0 && gx < W) sp = gy*W + gx;
        if (sp < 0) {
#pragma unroll
            for (int c = 0; c < 16; c++) {
                xs[0][threadIdx.x*18 + c] = 0.f;
                xs[1][threadIdx.x*18 + c] = 0.f;
            }
        }
    }
    const float* xb = x + (n*C + c00)*P + (sp < 0 ? 0 : sp);
    u32 xsa[2];
    xsa[0] = (u32)__cvta_generic_to_shared(&xs[0][threadIdx.x*18]);
    xsa[1] = (u32)__cvta_generic_to_shared(&xs[1][threadIdx.x*18]);

    if (sp >= 0) {
#pragma unroll
        for (int c = 0; c < 16; c++) cp4(xsa[0] + c*4, xb + c*P);
    }
    asm volatile("cp.async.commit_group;");

    for (int idx = threadIdx.x; idx < ENC*64; idx += 256) {
        int ch = idx >> 6, pp = idx & 63;
        int src = (n*ENC + ch)*P + (h0 + (pp>>3))*W + w0 + (pp&7);
        ms[ch*65 + pp] = g_m[src] + g_m2[src];
    }
    __syncthreads();

    float mk[25];
    {
        float mx = -1e30f;
#pragma unroll
        for (int k = 0; k < 25; k++) {
            mk[k] = ms[(k*4 + s)*65 + p];
            mx = fmaxf(mx, mk[k]);
        }
        float sum = 0.f;
#pragma unroll
        for (int k = 0; k < 25; k++) { mk[k] = __expf(mk[k] - mx); sum += mk[k]; }
        float inv = 1.f / sum;
#pragma unroll
        for (int k = 0; k < 25; k++) mk[k] *= inv;
    }

    float* ob = out + (size_t)(n*C + c00)*HO*WO + (size_t)(2*gh + si)*WO + 2*gw + sj;
    const int xbase = (h*12 + w)*18;

    for (int rr = 0; rr < 4; rr++) {
        asm volatile("cp.async.wait_group 0;");
        __syncthreads();
        if (rr < 3) {
            if (sp >= 0) {
                const float* src = xb + (rr + 1)*16*P;
                u32 d = xsa[(rr + 1) & 1];
#pragma unroll
                for (int c = 0; c < 16; c++) cp4(d + c*4, src + c*P);
            }
            asm volatile("cp.async.commit_group;");
        }
        const float* xsb = xs[rr & 1] + xbase;

        u64 acc[8];
#pragma unroll
        for (int q = 0; q < 8; q++) acc[q] = 0ull;
#pragma unroll
        for (int k = 0; k < 25; k++) {
            const float* xp = xsb + ((k/5)*12 + (k%5))*18;
            u64 md = dup2(mk[k]);
#pragma unroll
            for (int q = 0; q < 8; q++)
                acc[q] = fma2(*(const u64*)(xp + q*2), md, acc[q]);
        }
#pragma unroll
        for (int q = 0; q < 8; q++) {
            float lo, hi;
            unpack2(acc[q], lo, hi);
            ob[(size_t)(rr*16 + 2*q)*HO*WO]     = lo;
            ob[(size_t)(rr*16 + 2*q + 1)*HO*WO] = hi;
        }
    }
}

// ---------------------------------------------------------------------------
extern "C" void kernel_launch(void* const* d_in, const int* in_sizes, int n_in,
                              void* d_out, int out_size) {
    const float* x  = (const float*)d_in[0];
    const float* Wc = (const float*)d_in[1];
    const float* bc = (const float*)d_in[2];
    const float* We = (const float*)d_in[3];
    const float* be = (const float*)d_in[4];
    float* out = (float*)d_out;

    k_transpose <<<64, 256>>>(Wc);
    k_wpack     <<<144, 256>>>(We);
    k_compress  <<<dim3(128, NN), 128>>>(x, bc);
    k_encode    <<<dim3(16, NN, 8), 256>>>(be);
    k_reassemble<<<dim3(64, NN, 4), 256>>>(x, out);
}

// round 16
// speedup vs baseline: 1.0277x; 1.0277x over previous
#include <cuda_runtime.h>
#include <cstdint>

#define NN   4
#define C    256
#define H    64
#define W    64
#define P    (H*W)
#define CCH  64
#define K2   25
#define HO   128
#define WO   128
#define ENC  100

typedef unsigned long long u64;
typedef unsigned int u32;

__device__ __forceinline__ u64 pack2(float lo, float hi) {
    u64 r; asm("mov.b64 %0, {%1,%2};" : "=l"(r) : "f"(lo), "f"(hi)); return r;
}
__device__ __forceinline__ u64 dup2(float v) {
    u64 r; asm("mov.b64 %0, {%1,%1};" : "=l"(r) : "f"(v)); return r;
}
__device__ __forceinline__ void unpack2(u64 v, float& lo, float& hi) {
    asm("mov.b64 {%0,%1}, %2;" : "=f"(lo), "=f"(hi) : "l"(v));
}
__device__ __forceinline__ u64 fma2(u64 a, u64 b, u64 c) {
    u64 d; asm("fma.rn.f32x2 %0, %1, %2, %3;" : "=l"(d) : "l"(a), "l"(b), "l"(c)); return d;
}
__device__ __forceinline__ u64 add2(u64 a, u64 b) {
    u64 d; asm("add.rn.f32x2 %0, %1, %2;" : "=l"(d) : "l"(a), "l"(b)); return d;
}
__device__ __forceinline__ void cp4(u32 dst, const float* src) {
    asm volatile("cp.async.ca.shared.global [%0], [%1], 4;" :: "r"(dst), "l"(src));
}
__device__ __forceinline__ void cp16(u32 dst, const float* src) {
    asm volatile("cp.async.cg.shared.global [%0], [%1], 16;" :: "r"(dst), "l"(src));
}

// scratch (device globals; no allocations allowed)
__device__ float g_comp[NN*CCH*P];           // 4 MB
__device__ float g_m[NN*ENC*P];              // encoder logits, K quarter 0
__device__ float g_m2[NN*ENC*P];             // quarter 1
__device__ float g_m3[NN*ENC*P];             // quarter 2
__device__ float g_m4[NN*ENC*P];             // quarter 3
__device__ float g_wt[C*CCH];                // transposed compressor weights
__device__ float2 g_wp[4*8*8*9*14];          // packed encoder weights

// ---------------------------------------------------------------------------
// Kernel Prep: transpose Wc AND pack encoder weights (one launch).
// blocks 0..63: g_wt; blocks 64..189: g_wp.
// g_wp[ocg 4][round 8][c 8][tap 9][qq 14] float2 (oc pairs, last padded).
// ---------------------------------------------------------------------------
__global__ void k_prep(const float* __restrict__ Wc, const float* __restrict__ We) {
    if (blockIdx.x < 64) {
        int idx = blockIdx.x * 256 + threadIdx.x;   // 16384
        int oc = idx & 63, c = idx >> 6;
        g_wt[c*CCH + oc] = Wc[oc*C + c];
    } else {
        int idx = (blockIdx.x - 64) * 256 + threadIdx.x;  // 32256 entries
        if (idx >= 4*8*8*9*14) return;
        int qq  = idx % 14;
        int tap = (idx / 14) % 9;
        int c   = (idx / 126) % 8;
        int r   = (idx / 1008) % 8;
        int ocg = idx / 8064;
        int cs  = r*8 + c;
        int oc  = ocg*25 + 2*qq;
        float wa = (2*qq     < 25) ? We[(oc*CCH + cs)*9 + tap]       : 0.f;
        float wb = (2*qq + 1 < 25) ? We[((oc + 1)*CCH + cs)*9 + tap] : 0.f;
        g_wp[idx] = make_float2(wa, wb);
    }
}

// ---------------------------------------------------------------------------
// Kernel A: 1x1 conv compressor, 64oc x 32px tiles, packed f32x2 over px.
// ---------------------------------------------------------------------------
__global__ __launch_bounds__(128)
void k_compress(const float* __restrict__ x, const float* __restrict__ bc) {
    __shared__ __align__(16) float Ws[16][64];
    __shared__ __align__(16) float Xs[16][32];
    const int n  = blockIdx.y;
    const int p0 = blockIdx.x * 32;
    const int tx = threadIdx.x & 7;
    const int ty = threadIdx.x >> 3;

    u64 acc[4][2];
#pragma unroll
    for (int i = 0; i < 4; i++) { acc[i][0] = 0ull; acc[i][1] = 0ull; }

    for (int c0 = 0; c0 < C; c0 += 16) {
        __syncthreads();
        for (int i = threadIdx.x; i < 1024; i += 128) {
            int k = i >> 6, oc = i & 63;
            Ws[k][oc] = g_wt[(c0 + k)*CCH + oc];
        }
        for (int i = threadIdx.x; i < 512; i += 128) {
            int k = i >> 5, px = i & 31;
            Xs[k][px] = x[(n*C + c0 + k)*P + p0 + px];
        }
        __syncthreads();
#pragma unroll
        for (int k = 0; k < 16; k++) {
            float4 a = *(const float4*)&Ws[k][ty*4];
            u64 b01 = *(const u64*)&Xs[k][tx*4];
            u64 b23 = *(const u64*)&Xs[k][tx*4 + 2];
            float av[4] = {a.x, a.y, a.z, a.w};
#pragma unroll
            for (int i = 0; i < 4; i++) {
                u64 d = dup2(av[i]);
                acc[i][0] = fma2(d, b01, acc[i][0]);
                acc[i][1] = fma2(d, b23, acc[i][1]);
            }
        }
    }
#pragma unroll
    for (int i = 0; i < 4; i++) {
        int oc = ty*4 + i;
        u64 bd = dup2(bc[oc]);
        float* p = &g_comp[(n*CCH + oc)*P + p0 + tx*4];
        *(u64*)p       = add2(acc[i][0], bd);
        *(u64*)(p + 2) = add2(acc[i][1], bd);
    }
}

// ---------------------------------------------------------------------------
// Kernel B: 3x3 conv encoder. R13's proven mix (128 thr, 2px/thread, 13
// packed oc-pair accs) + FOUR-way K-split (kq: 16 ch each, 2 rounds) for
// 1024 blocks x 4 warps. cp.async double-buffered tile+weight staging.
// grid (16 tiles, 4 n, 4 ocg x 4 kq) = 1024 blocks x 128 thr.
// ---------------------------------------------------------------------------
__global__ __launch_bounds__(128)
void k_encode(const float* __restrict__ be) {
    __shared__ __align__(16) float tile[2][8*324];    // [c][18][18]
    __shared__ __align__(16) float2 wgt2[2][8*9*14];  // [c][tap][14 pairs]
    const int bx = blockIdx.x;
    const int h0 = (bx >> 2) * 16;
    const int w0 = (bx & 3) * 16;
    const int n  = blockIdx.y;
    const int ocg = blockIdx.z & 3;
    const int kq  = blockIdx.z >> 2;      // 0..3 K-quarter (16 ch)
    const int oc0 = ocg * 25;
    const int xg = threadIdx.x & 7;
    const int ty = threadIdx.x >> 3;   // 0..15

    // staging geometry (3 slots per thread, round-invariant)
    int sps[3]; bool oks[3];
#pragma unroll
    for (int j = 0; j < 3; j++) {
        int q = threadIdx.x + j*128;
        oks[j] = false; sps[j] = 0;
        if (q < 324) {
            int yy = q / 18, xw = q % 18;
            int gy = h0 + yy - 1, gx = w0 + xw - 1;
            if (gy >= 0 && gy < H && gx >= 0 && gx < W) {
                oks[j] = true; sps[j] = gy*W + gx;
            } else {
#pragma unroll
                for (int c = 0; c < 8; c++) {
                    tile[0][c*324 + q] = 0.f;
                    tile[1][c*324 + q] = 0.f;
                }
            }
        }
    }
    const float* cb = g_comp + n*CCH*P + kq*16*P;
    const float* wb = (const float*)(g_wp + ocg*8064 + kq*2016);  // float2 units

    u32 ta[2], wa[2];
    ta[0] = (u32)__cvta_generic_to_shared(&tile[0][0]);
    ta[1] = (u32)__cvta_generic_to_shared(&tile[1][0]);
    wa[0] = (u32)__cvta_generic_to_shared(&wgt2[0][0]);
    wa[1] = (u32)__cvta_generic_to_shared(&wgt2[1][0]);

    // stage round 0
#pragma unroll
    for (int j = 0; j < 3; j++) if (oks[j]) {
        int q = threadIdx.x + j*128;
#pragma unroll
        for (int c = 0; c < 8; c++)
            cp4(ta[0] + (c*324 + q)*4, cb + c*P + sps[j]);
    }
    for (int i = threadIdx.x; i < 504; i += 128)
        cp16(wa[0] + i*16, wb + i*4);
    asm volatile("cp.async.commit_group;");

    u64 accA[13], accB[13];
#pragma unroll
    for (int q = 0; q < 13; q++) { accA[q] = 0ull; accB[q] = 0ull; }

    for (int r = 0; r < 2; r++) {
        asm volatile("cp.async.wait_group 0;");
        __syncthreads();
        if (r < 1) {
            const float* cbn = cb + 8*P;
#pragma unroll
            for (int j = 0; j < 3; j++) if (oks[j]) {
                int q = threadIdx.x + j*128;
#pragma unroll
                for (int c = 0; c < 8; c++)
                    cp4(ta[1] + (c*324 + q)*4, cbn + c*P + sps[j]);
            }
            const float* wbn = wb + 2016;   // 1008 float2 per round
            for (int i = threadIdx.x; i < 504; i += 128)
                cp16(wa[1] + i*16, wbn + i*4);
            asm volatile("cp.async.commit_group;");
        }
        const float* tb = tile[r];
        const float2* wg = wgt2[r];
#pragma unroll 1
        for (int c = 0; c < 8; c++) {
            const int base = c*324 + ty*18 + xg*2;
#pragma unroll
            for (int ky = 0; ky < 3; ky++) {
                float2 fa = *(const float2*)&tb[base + ky*18];
                float2 fb = *(const float2*)&tb[base + ky*18 + 2];
                u64 dv[4];
                dv[0] = dup2(fa.x); dv[1] = dup2(fa.y);
                dv[2] = dup2(fb.x); dv[3] = dup2(fb.y);
#pragma unroll
                for (int kx = 0; kx < 3; kx++) {
                    u64 v0 = dv[kx];
                    u64 v1 = dv[kx + 1];
                    const float2* wp = &wg[(c*9 + ky*3 + kx)*14];
                    ulonglong2 w01 = *(const ulonglong2*)(wp);
                    ulonglong2 w23 = *(const ulonglong2*)(wp + 2);
                    ulonglong2 w45 = *(const ulonglong2*)(wp + 4);
                    ulonglong2 w67 = *(const ulonglong2*)(wp + 6);
                    ulonglong2 w89 = *(const ulonglong2*)(wp + 8);
                    ulonglong2 wAB = *(const ulonglong2*)(wp + 10);
                    u64 wC = *(const u64*)(wp + 12);
                    accA[0]  = fma2(v0, w01.x, accA[0]);  accB[0]  = fma2(v1, w01.x, accB[0]);
                    accA[1]  = fma2(v0, w01.y, accA[1]);  accB[1]  = fma2(v1, w01.y, accB[1]);
                    accA[2]  = fma2(v0, w23.x, accA[2]);  accB[2]  = fma2(v1, w23.x, accB[2]);
                    accA[3]  = fma2(v0, w23.y, accA[3]);  accB[3]  = fma2(v1, w23.y, accB[3]);
                    accA[4]  = fma2(v0, w45.x, accA[4]);  accB[4]  = fma2(v1, w45.x, accB[4]);
                    accA[5]  = fma2(v0, w45.y, accA[5]);  accB[5]  = fma2(v1, w45.y, accB[5]);
                    accA[6]  = fma2(v0, w67.x, accA[6]);  accB[6]  = fma2(v1, w67.x, accB[6]);
                    accA[7]  = fma2(v0, w67.y, accA[7]);  accB[7]  = fma2(v1, w67.y, accB[7]);
                    accA[8]  = fma2(v0, w89.x, accA[8]);  accB[8]  = fma2(v1, w89.x, accB[8]);
                    accA[9]  = fma2(v0, w89.y, accA[9]);  accB[9]  = fma2(v1, w89.y, accB[9]);
                    accA[10] = fma2(v0, wAB.x, accA[10]); accB[10] = fma2(v1, wAB.x, accB[10]);
                    accA[11] = fma2(v0, wAB.y, accA[11]); accB[11] = fma2(v1, wAB.y, accB[11]);
                    accA[12] = fma2(v0, wC,    accA[12]); accB[12] = fma2(v1, wC,    accB[12]);
                }
            }
        }
        __syncthreads();
    }

    float* __restrict__ gout = (kq == 0) ? g_m : (kq == 1) ? g_m2
                             : (kq == 2) ? g_m3 : g_m4;
    const int y = h0 + ty, xpx = w0 + xg*2;
#pragma unroll
    for (int q = 0; q < 13; q++) {
        int oc = oc0 + 2*q;
        float a0, a1, b0, b1;
        unpack2(accA[q], a0, a1);
        unpack2(accB[q], b0, b1);
        float bias0 = kq ? 0.f : be[oc];
        *(float2*)&gout[(n*ENC + oc)*P + y*W + xpx] = make_float2(a0 + bias0, b0 + bias0);
        if (2*q + 1 < 25) {
            float bias1 = kq ? 0.f : be[oc + 1];
            *(float2*)&gout[(n*ENC + oc + 1)*P + y*W + xpx] = make_float2(a1 + bias1, b1 + bias1);
        }
    }
}

// ---------------------------------------------------------------------------
// Kernel D: fused softmax + reassembly (scheme W, sum of 4 K-quarter bufs).
// ---------------------------------------------------------------------------
__global__ __launch_bounds__(256)
void k_reassemble(const float* __restrict__ x, float* __restrict__ out) {
    __shared__ float ms[ENC*65];
    __shared__ __align__(16) float xs[2][144*18];   // [spatial][ch pad 18]
    const int t   = blockIdx.x;
    const int n   = blockIdx.y;
    const int c00 = blockIdx.z * 64;
    const int h0 = (t >> 3) * 8, w0 = (t & 7) * 8;
    const int s  = threadIdx.x & 3;
    const int p  = threadIdx.x >> 2;
    const int h  = p >> 3, w = p & 7;
    const int gh = h0 + h, gw = w0 + w;
    const int si = s >> 1, sj = s & 1;

    int sp = -1;
    if (threadIdx.x < 144) {
        int yy = threadIdx.x / 12, xw = threadIdx.x % 12;
        int gy = h0 + yy - 2, gx = w0 + xw - 2;
        if (gy >= 0 && gy < H && gx >= 0 && gx < W) sp = gy*W + gx;
        if (sp < 0) {
#pragma unroll
            for (int c = 0; c < 16; c++) {
                xs[0][threadIdx.x*18 + c] = 0.f;
                xs[1][threadIdx.x*18 + c] = 0.f;
            }
        }
    }
    const float* xb = x + (n*C + c00)*P + (sp < 0 ? 0 : sp);
    u32 xsa[2];
    xsa[0] = (u32)__cvta_generic_to_shared(&xs[0][threadIdx.x*18]);
    xsa[1] = (u32)__cvta_generic_to_shared(&xs[1][threadIdx.x*18]);

    if (sp >= 0) {
#pragma unroll
        for (int c = 0; c < 16; c++) cp4(xsa[0] + c*4, xb + c*P);
    }
    asm volatile("cp.async.commit_group;");

    for (int idx = threadIdx.x; idx < ENC*64; idx += 256) {
        int ch = idx >> 6, pp = idx & 63;
        int src = (n*ENC + ch)*P + (h0 + (pp>>3))*W + w0 + (pp&7);
        ms[ch*65 + pp] = (g_m[src] + g_m2[src]) + (g_m3[src] + g_m4[src]);
    }
    __syncthreads();

    float mk[25];
    {
        float mx = -1e30f;
#pragma unroll
        for (int k = 0; k < 25; k++) {
            mk[k] = ms[(k*4 + s)*65 + p];
            mx = fmaxf(mx, mk[k]);
        }
        float sum = 0.f;
#pragma unroll
        for (int k = 0; k < 25; k++) { mk[k] = __expf(mk[k] - mx); sum += mk[k]; }
        float inv = 1.f / sum;
#pragma unroll
        for (int k = 0; k < 25; k++) mk[k] *= inv;
    }

    float* ob = out + (size_t)(n*C + c00)*HO*WO + (size_t)(2*gh + si)*WO + 2*gw + sj;
    const int xbase = (h*12 + w)*18;

    for (int rr = 0; rr < 4; rr++) {
        asm volatile("cp.async.wait_group 0;");
        __syncthreads();
        if (rr < 3) {
            if (sp >= 0) {
                const float* src = xb + (rr + 1)*16*P;
                u32 d = xsa[(rr + 1) & 1];
#pragma unroll
                for (int c = 0; c < 16; c++) cp4(d + c*4, src + c*P);
            }
            asm volatile("cp.async.commit_group;");
        }
        const float* xsb = xs[rr & 1] + xbase;

        u64 acc[8];
#pragma unroll
        for (int q = 0; q < 8; q++) acc[q] = 0ull;
#pragma unroll
        for (int k = 0; k < 25; k++) {
            const float* xp = xsb + ((k/5)*12 + (k%5))*18;
            u64 md = dup2(mk[k]);
#pragma unroll
            for (int q = 0; q < 8; q++)
                acc[q] = fma2(*(const u64*)(xp + q*2), md, acc[q]);
        }
#pragma unroll
        for (int q = 0; q < 8; q++) {
            float lo, hi;
            unpack2(acc[q], lo, hi);
            ob[(size_t)(rr*16 + 2*q)*HO*WO]     = lo;
            ob[(size_t)(rr*16 + 2*q + 1)*HO*WO] = hi;
        }
    }
}

// ---------------------------------------------------------------------------
extern "C" void kernel_launch(void* const* d_in, const int* in_sizes, int n_in,
                              void* d_out, int out_size) {
    const float* x  = (const float*)d_in[0];
    const float* Wc = (const float*)d_in[1];
    const float* bc = (const float*)d_in[2];
    const float* We = (const float*)d_in[3];
    const float* be = (const float*)d_in[4];
    float* out = (float*)d_out;

    k_prep      <<<190, 256>>>(Wc, We);
    k_compress  <<<dim3(128, NN), 128>>>(x, bc);
    k_encode    <<<dim3(16, NN, 16), 128>>>(be);
    k_reassemble<<<dim3(64, NN, 4), 256>>>(x, out);
}

// round 17
// speedup vs baseline: 1.2690x; 1.2348x over previous
#include <cuda_runtime.h>
#include <cstdint>

#define NN   4
#define C    256
#define H    64
#define W    64
#define P    (H*W)
#define CCH  64
#define K2   25
#define HO   128
#define WO   128
#define ENC  100

typedef unsigned long long u64;
typedef unsigned int u32;

__device__ __forceinline__ u64 pack2(float lo, float hi) {
    u64 r; asm("mov.b64 %0, {%1,%2};" : "=l"(r) : "f"(lo), "f"(hi)); return r;
}
__device__ __forceinline__ u64 dup2(float v) {
    u64 r; asm("mov.b64 %0, {%1,%1};" : "=l"(r) : "f"(v)); return r;
}
__device__ __forceinline__ void unpack2(u64 v, float& lo, float& hi) {
    asm("mov.b64 {%0,%1}, %2;" : "=f"(lo), "=f"(hi) : "l"(v));
}
__device__ __forceinline__ u64 fma2(u64 a, u64 b, u64 c) {
    u64 d; asm("fma.rn.f32x2 %0, %1, %2, %3;" : "=l"(d) : "l"(a), "l"(b), "l"(c)); return d;
}
__device__ __forceinline__ u64 add2(u64 a, u64 b) {
    u64 d; asm("add.rn.f32x2 %0, %1, %2;" : "=l"(d) : "l"(a), "l"(b)); return d;
}
__device__ __forceinline__ void cp4(u32 dst, const float* src) {
    asm volatile("cp.async.ca.shared.global [%0], [%1], 4;" :: "r"(dst), "l"(src));
}
__device__ __forceinline__ void cp16(u32 dst, const float* src) {
    asm volatile("cp.async.cg.shared.global [%0], [%1], 16;" :: "r"(dst), "l"(src));
}

// scratch (device globals; no allocations allowed)
__device__ float g_comp[NN*CCH*P];           // 4 MB
__device__ float g_m[NN*ENC*P];              // encoder logits, K-half 0
__device__ float g_m2[NN*ENC*P];             // encoder logits, K-half 1
__device__ float g_wt[C*CCH];                // transposed compressor weights
__device__ float2 g_wp[4*8*8*9*14];          // packed encoder weights

// ---------------------------------------------------------------------------
// Kernel Prep: transpose Wc AND pack encoder weights (one launch).
// blocks 0..63: g_wt; blocks 64..189: g_wp.
// ---------------------------------------------------------------------------
__global__ void k_prep(const float* __restrict__ Wc, const float* __restrict__ We) {
    if (blockIdx.x < 64) {
        int idx = blockIdx.x * 256 + threadIdx.x;   // 16384
        int oc = idx & 63, c = idx >> 6;
        g_wt[c*CCH + oc] = Wc[oc*C + c];
    } else {
        int idx = (blockIdx.x - 64) * 256 + threadIdx.x;  // 32256 entries
        if (idx >= 4*8*8*9*14) return;
        int qq  = idx % 14;
        int tap = (idx / 14) % 9;
        int c   = (idx / 126) % 8;
        int r   = (idx / 1008) % 8;
        int ocg = idx / 8064;
        int cs  = r*8 + c;
        int oc  = ocg*25 + 2*qq;
        float wa = (2*qq     < 25) ? We[(oc*CCH + cs)*9 + tap]       : 0.f;
        float wb = (2*qq + 1 < 25) ? We[((oc + 1)*CCH + cs)*9 + tap] : 0.f;
        g_wp[idx] = make_float2(wa, wb);
    }
}

// ---------------------------------------------------------------------------
// Kernel A v2: 1x1 conv compressor, 64oc x 64px blocks, cp.async double-
// buffered. 256 thr: ty(16)->4oc, tx(16)->4px. 16 K-rounds of 16 channels.
// grid (64 px-tiles, 4 n) = 256 blocks.
// ---------------------------------------------------------------------------
__global__ __launch_bounds__(256)
void k_compress(const float* __restrict__ x, const float* __restrict__ bc) {
    __shared__ __align__(16) float Ws[2][16][64];
    __shared__ __align__(16) float Xs[2][16][64];
    const int n  = blockIdx.y;
    const int p0 = blockIdx.x * 64;
    const int tx = threadIdx.x & 15;    // 4 px
    const int ty = threadIdx.x >> 4;    // 4 oc

    const int sk = threadIdx.x >> 4;    // staging: row 0..15
    const int sc = (threadIdx.x & 15) * 4;
    u32 wsa[2], xsa[2];
    wsa[0] = (u32)__cvta_generic_to_shared(&Ws[0][sk][sc]);
    wsa[1] = (u32)__cvta_generic_to_shared(&Ws[1][sk][sc]);
    xsa[0] = (u32)__cvta_generic_to_shared(&Xs[0][sk][sc]);
    xsa[1] = (u32)__cvta_generic_to_shared(&Xs[1][sk][sc]);
    const float* wsrc = &g_wt[sk*CCH + sc];            // + r*16*CCH
    const float* xsrc = &x[(n*C + sk)*P + p0 + sc];    // + r*16*P

    // stage round 0
    cp16(wsa[0], wsrc);
    cp16(xsa[0], xsrc);
    asm volatile("cp.async.commit_group;");

    u64 acc[4][2];
#pragma unroll
    for (int i = 0; i < 4; i++) { acc[i][0] = 0ull; acc[i][1] = 0ull; }

    for (int r = 0; r < 16; r++) {
        asm volatile("cp.async.wait_group 0;");
        __syncthreads();
        if (r < 15) {
            int nb = (r + 1) & 1;
            cp16(wsa[nb], wsrc + (r + 1)*16*CCH);
            cp16(xsa[nb], xsrc + (r + 1)*16*P);
            asm volatile("cp.async.commit_group;");
        }
        const int b = r & 1;
#pragma unroll
        for (int k = 0; k < 16; k++) {
            float4 a = *(const float4*)&Ws[b][k][ty*4];
            u64 b01 = *(const u64*)&Xs[b][k][tx*4];
            u64 b23 = *(const u64*)&Xs[b][k][tx*4 + 2];
            float av[4] = {a.x, a.y, a.z, a.w};
#pragma unroll
            for (int i = 0; i < 4; i++) {
                u64 d = dup2(av[i]);
                acc[i][0] = fma2(d, b01, acc[i][0]);
                acc[i][1] = fma2(d, b23, acc[i][1]);
            }
        }
        __syncthreads();
    }
#pragma unroll
    for (int i = 0; i < 4; i++) {
        int oc = ty*4 + i;
        u64 bd = dup2(bc[oc]);
        float* p = &g_comp[(n*CCH + oc)*P + p0 + tx*4];
        *(u64*)p       = add2(acc[i][0], bd);
        *(u64*)(p + 2) = add2(acc[i][1], bd);
    }
}

// ---------------------------------------------------------------------------
// Kernel B: 3x3 conv encoder (R13: 128 thr, 2px/thread, 13 oc-pair accs,
// 2-way K-split, cp.async double-buffered). grid (16,4,8) = 512 blocks.
// ---------------------------------------------------------------------------
__global__ __launch_bounds__(128)
void k_encode(const float* __restrict__ be) {
    __shared__ __align__(16) float tile[2][8*324];    // [c][18][18]
    __shared__ __align__(16) float2 wgt2[2][8*9*14];  // [c][tap][14 pairs]
    const int bx = blockIdx.x;
    const int h0 = (bx >> 2) * 16;
    const int w0 = (bx & 3) * 16;
    const int n  = blockIdx.y;
    const int ocg = blockIdx.z & 3;
    const int kh  = blockIdx.z >> 2;
    const int oc0 = ocg * 25;
    const int xg = threadIdx.x & 7;
    const int ty = threadIdx.x >> 3;   // 0..15

    int sps[3]; bool oks[3];
#pragma unroll
    for (int j = 0; j < 3; j++) {
        int q = threadIdx.x + j*128;
        oks[j] = false; sps[j] = 0;
        if (q < 324) {
            int yy = q / 18, xw = q % 18;
            int gy = h0 + yy - 1, gx = w0 + xw - 1;
            if (gy >= 0 && gy < H && gx >= 0 && gx < W) {
                oks[j] = true; sps[j] = gy*W + gx;
            } else {
#pragma unroll
                for (int c = 0; c < 8; c++) {
                    tile[0][c*324 + q] = 0.f;
                    tile[1][c*324 + q] = 0.f;
                }
            }
        }
    }
    const float* cb = g_comp + n*CCH*P + kh*32*P;
    const float* wb = (const float*)(g_wp + ocg*8064 + kh*4032);

    u32 ta[2], wa[2];
    ta[0] = (u32)__cvta_generic_to_shared(&tile[0][0]);
    ta[1] = (u32)__cvta_generic_to_shared(&tile[1][0]);
    wa[0] = (u32)__cvta_generic_to_shared(&wgt2[0][0]);
    wa[1] = (u32)__cvta_generic_to_shared(&wgt2[1][0]);

#pragma unroll
    for (int j = 0; j < 3; j++) if (oks[j]) {
        int q = threadIdx.x + j*128;
#pragma unroll
        for (int c = 0; c < 8; c++)
            cp4(ta[0] + (c*324 + q)*4, cb + c*P + sps[j]);
    }
    for (int i = threadIdx.x; i < 504; i += 128)
        cp16(wa[0] + i*16, wb + i*4);
    asm volatile("cp.async.commit_group;");

    u64 accA[13], accB[13];
#pragma unroll
    for (int q = 0; q < 13; q++) { accA[q] = 0ull; accB[q] = 0ull; }

    for (int r = 0; r < 4; r++) {
        asm volatile("cp.async.wait_group 0;");
        __syncthreads();
        if (r < 3) {
            int nb = (r + 1) & 1;
            const float* cbn = cb + (r + 1)*8*P;
#pragma unroll
            for (int j = 0; j < 3; j++) if (oks[j]) {
                int q = threadIdx.x + j*128;
#pragma unroll
                for (int c = 0; c < 8; c++)
                    cp4(ta[nb] + (c*324 + q)*4, cbn + c*P + sps[j]);
            }
            const float* wbn = wb + (r + 1)*2016;
            for (int i = threadIdx.x; i < 504; i += 128)
                cp16(wa[nb] + i*16, wbn + i*4);
            asm volatile("cp.async.commit_group;");
        }
        const float* tb = tile[r & 1];
        const float2* wg = wgt2[r & 1];
#pragma unroll 1
        for (int c = 0; c < 8; c++) {
            const int base = c*324 + ty*18 + xg*2;
#pragma unroll
            for (int ky = 0; ky < 3; ky++) {
                float2 fa = *(const float2*)&tb[base + ky*18];
                float2 fb = *(const float2*)&tb[base + ky*18 + 2];
                u64 dv[4];
                dv[0] = dup2(fa.x); dv[1] = dup2(fa.y);
                dv[2] = dup2(fb.x); dv[3] = dup2(fb.y);
#pragma unroll
                for (int kx = 0; kx < 3; kx++) {
                    u64 v0 = dv[kx];
                    u64 v1 = dv[kx + 1];
                    const float2* wp = &wg[(c*9 + ky*3 + kx)*14];
                    ulonglong2 w01 = *(const ulonglong2*)(wp);
                    ulonglong2 w23 = *(const ulonglong2*)(wp + 2);
                    ulonglong2 w45 = *(const ulonglong2*)(wp + 4);
                    ulonglong2 w67 = *(const ulonglong2*)(wp + 6);
                    ulonglong2 w89 = *(const ulonglong2*)(wp + 8);
                    ulonglong2 wAB = *(const ulonglong2*)(wp + 10);
                    u64 wC = *(const u64*)(wp + 12);
                    accA[0]  = fma2(v0, w01.x, accA[0]);  accB[0]  = fma2(v1, w01.x, accB[0]);
                    accA[1]  = fma2(v0, w01.y, accA[1]);  accB[1]  = fma2(v1, w01.y, accB[1]);
                    accA[2]  = fma2(v0, w23.x, accA[2]);  accB[2]  = fma2(v1, w23.x, accB[2]);
                    accA[3]  = fma2(v0, w23.y, accA[3]);  accB[3]  = fma2(v1, w23.y, accB[3]);
                    accA[4]  = fma2(v0, w45.x, accA[4]);  accB[4]  = fma2(v1, w45.x, accB[4]);
                    accA[5]  = fma2(v0, w45.y, accA[5]);  accB[5]  = fma2(v1, w45.y, accB[5]);
                    accA[6]  = fma2(v0, w67.x, accA[6]);  accB[6]  = fma2(v1, w67.x, accB[6]);
                    accA[7]  = fma2(v0, w67.y, accA[7]);  accB[7]  = fma2(v1, w67.y, accB[7]);
                    accA[8]  = fma2(v0, w89.x, accA[8]);  accB[8]  = fma2(v1, w89.x, accB[8]);
                    accA[9]  = fma2(v0, w89.y, accA[9]);  accB[9]  = fma2(v1, w89.y, accB[9]);
                    accA[10] = fma2(v0, wAB.x, accA[10]); accB[10] = fma2(v1, wAB.x, accB[10]);
                    accA[11] = fma2(v0, wAB.y, accA[11]); accB[11] = fma2(v1, wAB.y, accB[11]);
                    accA[12] = fma2(v0, wC,    accA[12]); accB[12] = fma2(v1, wC,    accB[12]);
                }
            }
        }
        __syncthreads();
    }

    float* __restrict__ gout = kh ? g_m2 : g_m;
    const int y = h0 + ty, xpx = w0 + xg*2;
#pragma unroll
    for (int q = 0; q < 13; q++) {
        int oc = oc0 + 2*q;
        float a0, a1, b0, b1;
        unpack2(accA[q], a0, a1);
        unpack2(accB[q], b0, b1);
        float bias0 = kh ? 0.f : be[oc];
        *(float2*)&gout[(n*ENC + oc)*P + y*W + xpx] = make_float2(a0 + bias0, b0 + bias0);
        if (2*q + 1 < 25) {
            float bias1 = kh ? 0.f : be[oc + 1];
            *(float2*)&gout[(n*ENC + oc + 1)*P + y*W + xpx] = make_float2(a1 + bias1, b1 + bias1);
        }
    }
}

// ---------------------------------------------------------------------------
// Kernel D: fused softmax + reassembly (R13 scheme W, g_m + g_m2 sum).
// ---------------------------------------------------------------------------
__global__ __launch_bounds__(256)
void k_reassemble(const float* __restrict__ x, float* __restrict__ out) {
    __shared__ float ms[ENC*65];
    __shared__ __align__(16) float xs[2][144*18];   // [spatial][ch pad 18]
    const int t   = blockIdx.x;
    const int n   = blockIdx.y;
    const int c00 = blockIdx.z * 64;
    const int h0 = (t >> 3) * 8, w0 = (t & 7) * 8;
    const int s  = threadIdx.x & 3;
    const int p  = threadIdx.x >> 2;
    const int h  = p >> 3, w = p & 7;
    const int gh = h0 + h, gw = w0 + w;
    const int si = s >> 1, sj = s & 1;

    int sp = -1;
    if (threadIdx.x < 144) {
        int yy = threadIdx.x / 12, xw = threadIdx.x % 12;
        int gy = h0 + yy - 2, gx = w0 + xw - 2;
        if (gy >= 0 && gy < H && gx >= 0 && gx < W) sp = gy*W + gx;
        if (sp < 0) {
#pragma unroll
            for (int c = 0; c < 16; c++) {
                xs[0][threadIdx.x*18 + c] = 0.f;
                xs[1][threadIdx.x*18 + c] = 0.f;
            }
        }
    }
    const float* xb = x + (n*C + c00)*P + (sp < 0 ? 0 : sp);
    u32 xsa[2];
    xsa[0] = (u32)__cvta_generic_to_shared(&xs[0][threadIdx.x*18]);
    xsa[1] = (u32)__cvta_generic_to_shared(&xs[1][threadIdx.x*18]);

    if (sp >= 0) {
#pragma unroll
        for (int c = 0; c < 16; c++) cp4(xsa[0] + c*4, xb + c*P);
    }
    asm volatile("cp.async.commit_group;");

    for (int idx = threadIdx.x; idx < ENC*64; idx += 256) {
        int ch = idx >> 6, pp = idx & 63;
        int src = (n*ENC + ch)*P + (h0 + (pp>>3))*W + w0 + (pp&7);
        ms[ch*65 + pp] = g_m[src] + g_m2[src];
    }
    __syncthreads();

    float mk[25];
    {
        float mx = -1e30f;
#pragma unroll
        for (int k = 0; k < 25; k++) {
            mk[k] = ms[(k*4 + s)*65 + p];
            mx = fmaxf(mx, mk[k]);
        }
        float sum = 0.f;
#pragma unroll
        for (int k = 0; k < 25; k++) { mk[k] = __expf(mk[k] - mx); sum += mk[k]; }
        float inv = 1.f / sum;
#pragma unroll
        for (int k = 0; k < 25; k++) mk[k] *= inv;
    }

    float* ob = out + (size_t)(n*C + c00)*HO*WO + (size_t)(2*gh + si)*WO + 2*gw + sj;
    const int xbase = (h*12 + w)*18;

    for (int rr = 0; rr < 4; rr++) {
        asm volatile("cp.async.wait_group 0;");
        __syncthreads();
        if (rr < 3) {
            if (sp >= 0) {
                const float* src = xb + (rr + 1)*16*P;
                u32 d = xsa[(rr + 1) & 1];
#pragma unroll
                for (int c = 0; c < 16; c++) cp4(d + c*4, src + c*P);
            }
            asm volatile("cp.async.commit_group;");
        }
        const float* xsb = xs[rr & 1] + xbase;

        u64 acc[8];
#pragma unroll
        for (int q = 0; q < 8; q++) acc[q] = 0ull;
#pragma unroll
        for (int k = 0; k < 25; k++) {
            const float* xp = xsb + ((k/5)*12 + (k%5))*18;
            u64 md = dup2(mk[k]);
#pragma unroll
            for (int q = 0; q < 8; q++)
                acc[q] = fma2(*(const u64*)(xp + q*2), md, acc[q]);
        }
#pragma unroll
        for (int q = 0; q < 8; q++) {
            float lo, hi;
            unpack2(acc[q], lo, hi);
            ob[(size_t)(rr*16 + 2*q)*HO*WO]     = lo;
            ob[(size_t)(rr*16 + 2*q + 1)*HO*WO] = hi;
        }
    }
}

// ---------------------------------------------------------------------------
extern "C" void kernel_launch(void* const* d_in, const int* in_sizes, int n_in,
                              void* d_out, int out_size) {
    const float* x  = (const float*)d_in[0];
    const float* Wc = (const float*)d_in[1];
    const float* bc = (const float*)d_in[2];
    const float* We = (const float*)d_in[3];
    const float* be = (const float*)d_in[4];
    float* out = (float*)d_out;

    k_prep      <<<190, 256>>>(Wc, We);
    k_compress  <<<dim3(64, NN), 256>>>(x, bc);
    k_encode    <<<dim3(16, NN, 8), 128>>>(be);
    k_reassemble<<<dim3(64, NN, 4), 256>>>(x, out);
}